// round 1
// baseline (speedup 1.0000x reference)
#include <cuda_runtime.h>
#include <math.h>

// ---------------- problem constants ----------------
#define NB    4
#define S_LEN 2048
#define DIM   512
#define NH    8
#define HD    64
#define TOK   (NB * S_LEN)          // 8192

// ---------------- scratch (no allocations allowed) ----------------
__device__ float g_h[TOK * DIM];          // LN output (reused for LN1 and LN2)
__device__ float g_qkv[TOK * 3 * DIM];    // QKV, rope applied in-place
__device__ float g_att[TOK * DIM];        // attention output (b,s,h,d)
__device__ float g_x1[TOK * DIM];         // residual after proj
__device__ float g_mid[TOK * 4 * DIM];    // FC1/GELU output

// ---------------- LayerNorm: one block (256 thr) per row of 512 ----------------
__global__ void __launch_bounds__(256) ln_kernel(const float* __restrict__ x,
                                                 const float* __restrict__ g,
                                                 const float* __restrict__ b,
                                                 float* __restrict__ out)
{
    int row = blockIdx.x;
    int t = threadIdx.x;                       // 0..255, 2 elems each
    const float2* xr = (const float2*)(x + (size_t)row * DIM);
    float2 v = xr[t];
    float s = v.x + v.y;
    float ss = v.x * v.x + v.y * v.y;
#pragma unroll
    for (int m = 16; m; m >>= 1) {
        s  += __shfl_xor_sync(0xffffffffu, s, m);
        ss += __shfl_xor_sync(0xffffffffu, ss, m);
    }
    __shared__ float sh[16];
    int w = t >> 5;
    if ((t & 31) == 0) { sh[w] = s; sh[8 + w] = ss; }
    __syncthreads();
    s = 0.f; ss = 0.f;
#pragma unroll
    for (int i = 0; i < 8; i++) { s += sh[i]; ss += sh[8 + i]; }
    float mu  = s * (1.f / DIM);
    float var = ss * (1.f / DIM) - mu * mu;
    float inv = rsqrtf(var + 1e-5f);
    float2 gg = ((const float2*)g)[t];
    float2 bb = ((const float2*)b)[t];
    float2 o;
    o.x = (v.x - mu) * inv * gg.x + bb.x;
    o.y = (v.y - mu) * inv * gg.y + bb.y;
    ((float2*)(out + (size_t)row * DIM))[t] = o;
}

// ---------------- RoPE applied in-place to q and k slices of qkv ----------------
// thread t -> (token, head, d) with d in [0,32); handles pair (d, d+32) of q and k
__global__ void __launch_bounds__(256) rope_kernel(float* __restrict__ qkv,
                                                   const float* __restrict__ cb,
                                                   const float* __restrict__ sb)
{
    int t = blockIdx.x * blockDim.x + threadIdx.x;   // 0 .. TOK*NH*32-1
    if (t >= TOK * NH * 32) return;
    int d   = t & 31;
    int h   = (t >> 5) & 7;
    int tok = t >> 8;
    int s   = tok & (S_LEN - 1);
    float c0 = cb[s * HD + d],      c1 = cb[s * HD + d + 32];
    float s0 = sb[s * HD + d],      s1 = sb[s * HD + d + 32];
    float* row = qkv + (size_t)tok * (3 * DIM);
    float* q = row + h * HD;
    float q0 = q[d], q1 = q[d + 32];
    q[d]      = q0 * c0 - q1 * s0;
    q[d + 32] = q1 * c1 + q0 * s1;
    float* k = row + DIM + h * HD;
    float k0 = k[d], k1 = k[d + 32];
    k[d]      = k0 * c0 - k1 * s0;
    k[d + 32] = k1 * c1 + k0 * s1;
}

// ---------------- generic tiled GEMM with fused epilogue ----------------
// C[M,N] = A[M,K] @ B[K,N] + bias   (EPI==1: gelu; EPI==2: += R)
// BM=BN=64, BK=16, 128 threads, 4x8 micro-tile per thread
__device__ __forceinline__ float gelu_f(float x)
{
    return 0.5f * x * (1.f + erff(x * 0.7071067811865476f));
}

template <int EPI>
__global__ void __launch_bounds__(128) gemm_kernel(const float* __restrict__ A,
                                                   const float* __restrict__ B,
                                                   const float* __restrict__ bias,
                                                   const float* __restrict__ R,
                                                   float* __restrict__ C,
                                                   int M, int N, int K)
{
    __shared__ __align__(16) float As[16][68];   // transposed: As[k][m]
    __shared__ __align__(16) float Bs[16][64];

    int tid = threadIdx.x;
    int tx = tid & 7, ty = tid >> 3;
    int m0 = blockIdx.y * 64, n0 = blockIdx.x * 64;

    float acc[4][8];
#pragma unroll
    for (int i = 0; i < 4; i++)
#pragma unroll
        for (int j = 0; j < 8; j++) acc[i][j] = 0.f;

    for (int k0 = 0; k0 < K; k0 += 16) {
        // A tile 64x16 (256 float4), stored transposed
#pragma unroll
        for (int it = 0; it < 2; ++it) {
            int i = tid + it * 128;
            int r = i >> 2, c = i & 3;
            float4 v = *(const float4*)&A[(size_t)(m0 + r) * K + k0 + c * 4];
            As[c * 4 + 0][r] = v.x; As[c * 4 + 1][r] = v.y;
            As[c * 4 + 2][r] = v.z; As[c * 4 + 3][r] = v.w;
        }
        // B tile 16x64 (256 float4)
#pragma unroll
        for (int it = 0; it < 2; ++it) {
            int i = tid + it * 128;
            int r = i >> 4, c = i & 15;
            *(float4*)&Bs[r][c * 4] = *(const float4*)&B[(size_t)(k0 + r) * N + n0 + c * 4];
        }
        __syncthreads();
#pragma unroll
        for (int k = 0; k < 16; k++) {
            float4 a  = *(const float4*)&As[k][ty * 4];
            float4 b0 = *(const float4*)&Bs[k][tx * 8];
            float4 b1 = *(const float4*)&Bs[k][tx * 8 + 4];
            float av[4] = {a.x, a.y, a.z, a.w};
            float bv[8] = {b0.x, b0.y, b0.z, b0.w, b1.x, b1.y, b1.z, b1.w};
#pragma unroll
            for (int i = 0; i < 4; i++)
#pragma unroll
                for (int j = 0; j < 8; j++) acc[i][j] += av[i] * bv[j];
        }
        __syncthreads();
    }

    // epilogue
    float4 bias0 = *(const float4*)&bias[n0 + tx * 8];
    float4 bias1 = *(const float4*)&bias[n0 + tx * 8 + 4];
    float bb[8] = {bias0.x, bias0.y, bias0.z, bias0.w, bias1.x, bias1.y, bias1.z, bias1.w};
#pragma unroll
    for (int i = 0; i < 4; i++) {
        int m = m0 + ty * 4 + i;
        size_t off = (size_t)m * N + n0 + tx * 8;
        float vv[8];
#pragma unroll
        for (int j = 0; j < 8; j++) {
            float v = acc[i][j] + bb[j];
            if (EPI == 1) v = gelu_f(v);
            vv[j] = v;
        }
        if (EPI == 2) {
            float4 r0 = *(const float4*)&R[off];
            float4 r1 = *(const float4*)&R[off + 4];
            vv[0] += r0.x; vv[1] += r0.y; vv[2] += r0.z; vv[3] += r0.w;
            vv[4] += r1.x; vv[5] += r1.y; vv[6] += r1.z; vv[7] += r1.w;
        }
        *(float4*)&C[off]     = make_float4(vv[0], vv[1], vv[2], vv[3]);
        *(float4*)&C[off + 4] = make_float4(vv[4], vv[5], vv[6], vv[7]);
    }
}

// ---------------- flash attention: grid (S/64, NH, NB), 128 threads ----------------
// dynamic smem layout: Qs[64][66] | Kt[64][64] | Vs[64][64] | Ps[64][66]
#define ATT_SMEM_FLOATS (64 * 66 + 64 * 64 + 64 * 64 + 64 * 66)

__global__ void __launch_bounds__(128) attn_kernel(const float* __restrict__ qkv,
                                                   float* __restrict__ out)
{
    extern __shared__ __align__(16) float smem[];
    float (*Qs)[66] = (float(*)[66])(smem);
    float (*Kt)[64] = (float(*)[64])(smem + 64 * 66);
    float (*Vs)[64] = (float(*)[64])(smem + 64 * 66 + 64 * 64);
    float (*Ps)[66] = (float(*)[66])(smem + 64 * 66 + 2 * 64 * 64);

    int tid = threadIdx.x, tx = tid & 7, ty = tid >> 3;
    int qt = blockIdx.x, h = blockIdx.y, b = blockIdx.z;

    const float* base = qkv + (size_t)b * S_LEN * (3 * DIM);
    const float* Qg = base + h * HD;
    const float* Kg = base + DIM + h * HD;
    const float* Vg = base + 2 * DIM + h * HD;

    // load Q tile (64 rows x 64 d)
#pragma unroll
    for (int it = 0; it < 8; ++it) {
        int i = tid + it * 128;
        int r = i >> 4, c = i & 15;
        float4 v = *(const float4*)&Qg[(size_t)(qt * 64 + r) * (3 * DIM) + c * 4];
        Qs[r][c * 4 + 0] = v.x; Qs[r][c * 4 + 1] = v.y;
        Qs[r][c * 4 + 2] = v.z; Qs[r][c * 4 + 3] = v.w;
    }

    float m_r[4], l_r[4], accO[4][8];
#pragma unroll
    for (int i = 0; i < 4; i++) {
        m_r[i] = -1e30f; l_r[i] = 0.f;
#pragma unroll
        for (int j = 0; j < 8; j++) accO[i][j] = 0.f;
    }
    const float scale = 0.125f;   // 1/sqrt(64)

    for (int nt = 0; nt < S_LEN / 64; ++nt) {
        __syncthreads();   // previous PV reads of Kt/Vs done
        // load K (transposed -> Kt[d][col]) and V (Vs[row][d])
#pragma unroll
        for (int it = 0; it < 8; ++it) {
            int i = tid + it * 128;
            int r = i >> 4, c = i & 15;
            size_t go = (size_t)(nt * 64 + r) * (3 * DIM) + c * 4;
            float4 kv = *(const float4*)&Kg[go];
            Kt[c * 4 + 0][r] = kv.x; Kt[c * 4 + 1][r] = kv.y;
            Kt[c * 4 + 2][r] = kv.z; Kt[c * 4 + 3][r] = kv.w;
            *(float4*)&Vs[r][c * 4] = *(const float4*)&Vg[go];
        }
        __syncthreads();

        // S = Q K^T (4x8 per thread)
        float s[4][8];
#pragma unroll
        for (int i = 0; i < 4; i++)
#pragma unroll
            for (int j = 0; j < 8; j++) s[i][j] = 0.f;
#pragma unroll 16
        for (int d = 0; d < 64; ++d) {
            float a0 = Qs[ty * 4 + 0][d], a1 = Qs[ty * 4 + 1][d];
            float a2 = Qs[ty * 4 + 2][d], a3 = Qs[ty * 4 + 3][d];
            float4 k0 = *(const float4*)&Kt[d][tx * 8];
            float4 k1 = *(const float4*)&Kt[d][tx * 8 + 4];
            float kv[8] = {k0.x, k0.y, k0.z, k0.w, k1.x, k1.y, k1.z, k1.w};
#pragma unroll
            for (int j = 0; j < 8; j++) {
                s[0][j] += a0 * kv[j]; s[1][j] += a1 * kv[j];
                s[2][j] += a2 * kv[j]; s[3][j] += a3 * kv[j];
            }
        }

        // online softmax update
#pragma unroll
        for (int i = 0; i < 4; i++) {
            float mt = -1e30f;
#pragma unroll
            for (int j = 0; j < 8; j++) { s[i][j] *= scale; mt = fmaxf(mt, s[i][j]); }
            mt = fmaxf(mt, __shfl_xor_sync(0xffffffffu, mt, 1));
            mt = fmaxf(mt, __shfl_xor_sync(0xffffffffu, mt, 2));
            mt = fmaxf(mt, __shfl_xor_sync(0xffffffffu, mt, 4));
            float mn = fmaxf(m_r[i], mt);
            float alpha = __expf(m_r[i] - mn);
            float rs = 0.f;
#pragma unroll
            for (int j = 0; j < 8; j++) {
                float p = __expf(s[i][j] - mn);
                Ps[ty * 4 + i][tx * 8 + j] = p;
                rs += p;
            }
            rs += __shfl_xor_sync(0xffffffffu, rs, 1);
            rs += __shfl_xor_sync(0xffffffffu, rs, 2);
            rs += __shfl_xor_sync(0xffffffffu, rs, 4);
            l_r[i] = l_r[i] * alpha + rs;
            m_r[i] = mn;
#pragma unroll
            for (int j = 0; j < 8; j++) accO[i][j] *= alpha;
        }
        __syncthreads();   // Ps visible

        // O += P @ V
#pragma unroll 16
        for (int j = 0; j < 64; ++j) {
            float p0 = Ps[ty * 4 + 0][j], p1 = Ps[ty * 4 + 1][j];
            float p2 = Ps[ty * 4 + 2][j], p3 = Ps[ty * 4 + 3][j];
            float4 v0 = *(const float4*)&Vs[j][tx * 8];
            float4 v1 = *(const float4*)&Vs[j][tx * 8 + 4];
            float vv[8] = {v0.x, v0.y, v0.z, v0.w, v1.x, v1.y, v1.z, v1.w};
#pragma unroll
            for (int c = 0; c < 8; c++) {
                accO[0][c] += p0 * vv[c]; accO[1][c] += p1 * vv[c];
                accO[2][c] += p2 * vv[c]; accO[3][c] += p3 * vv[c];
            }
        }
    }

    // write O / l to (b, s, h*HD + d) layout
#pragma unroll
    for (int i = 0; i < 4; i++) {
        float inv = 1.f / l_r[i];
        int row = b * S_LEN + qt * 64 + ty * 4 + i;
        size_t off = (size_t)row * DIM + h * HD + tx * 8;
        *(float4*)&out[off] = make_float4(accO[i][0] * inv, accO[i][1] * inv,
                                          accO[i][2] * inv, accO[i][3] * inv);
        *(float4*)&out[off + 4] = make_float4(accO[i][4] * inv, accO[i][5] * inv,
                                              accO[i][6] * inv, accO[i][7] * inv);
    }
}

// ---------------- launcher ----------------
extern "C" void kernel_launch(void* const* d_in, const int* in_sizes, int n_in,
                              void* d_out, int out_size)
{
    const float* x        = (const float*)d_in[0];
    const float* rope_cos = (const float*)d_in[1];
    const float* rope_sin = (const float*)d_in[2];
    const float* n1g      = (const float*)d_in[3];
    const float* n1b      = (const float*)d_in[4];
    const float* n2g      = (const float*)d_in[5];
    const float* n2b      = (const float*)d_in[6];
    const float* w_qkv    = (const float*)d_in[7];
    const float* b_qkv    = (const float*)d_in[8];
    const float* w_proj   = (const float*)d_in[9];
    const float* b_proj   = (const float*)d_in[10];
    const float* w_fc1    = (const float*)d_in[11];
    const float* b_fc1    = (const float*)d_in[12];
    const float* w_fc2    = (const float*)d_in[13];
    const float* b_fc2    = (const float*)d_in[14];
    float* out = (float*)d_out;

    float *ph, *pqkv, *patt, *px1, *pmid;
    cudaGetSymbolAddress((void**)&ph,   g_h);
    cudaGetSymbolAddress((void**)&pqkv, g_qkv);
    cudaGetSymbolAddress((void**)&patt, g_att);
    cudaGetSymbolAddress((void**)&px1,  g_x1);
    cudaGetSymbolAddress((void**)&pmid, g_mid);

    // opt-in dynamic smem for attention (66.5 KB); idempotent, capture-safe
    cudaFuncSetAttribute(attn_kernel, cudaFuncAttributeMaxDynamicSharedMemorySize,
                         ATT_SMEM_FLOATS * (int)sizeof(float));

    // 1) LN1
    ln_kernel<<<TOK, 256>>>(x, n1g, n1b, ph);
    // 2) QKV GEMM + bias
    gemm_kernel<0><<<dim3(3 * DIM / 64, TOK / 64), 128>>>(ph, w_qkv, b_qkv, nullptr, pqkv,
                                                          TOK, 3 * DIM, DIM);
    // 3) RoPE in place
    rope_kernel<<<(TOK * NH * 32 + 255) / 256, 256>>>(pqkv, rope_cos, rope_sin);
    // 4) attention
    attn_kernel<<<dim3(S_LEN / 64, NH, NB), 128, ATT_SMEM_FLOATS * sizeof(float)>>>(pqkv, patt);
    // 5) proj + bias + residual(x)
    gemm_kernel<2><<<dim3(DIM / 64, TOK / 64), 128>>>(patt, w_proj, b_proj, x, px1,
                                                      TOK, DIM, DIM);
    // 6) LN2
    ln_kernel<<<TOK, 256>>>(px1, n2g, n2b, ph);
    // 7) FC1 + bias + GELU
    gemm_kernel<1><<<dim3(4 * DIM / 64, TOK / 64), 128>>>(ph, w_fc1, b_fc1, nullptr, pmid,
                                                          TOK, 4 * DIM, DIM);
    // 8) FC2 + bias + residual(x1) -> out
    gemm_kernel<2><<<dim3(DIM / 64, TOK / 64), 128>>>(pmid, w_fc2, b_fc2, px1, out,
                                                      TOK, DIM, 4 * DIM);
}